// round 5
// baseline (speedup 1.0000x reference)
#include <cuda_runtime.h>
#include <math.h>

#define TOK_TOTAL 57344   // B*N = 8*7168
#define U_TOK     49152
#define N_TOK     7168

typedef unsigned long long u64;

// scratch: z1 = LN1(attention output), [B*N, 64] fp32
__device__ float g_z1[TOK_TOTAL * 64];

// ---------------- packed f32x2 helpers (sm_100+) ----------------
__device__ __forceinline__ u64 pk2(float x, float y) {
    u64 r; asm("mov.b64 %0, {%1,%2};" : "=l"(r) : "f"(x), "f"(y)); return r;
}
__device__ __forceinline__ float2 up2(u64 v) {
    float2 f; asm("mov.b64 {%0,%1}, %2;" : "=f"(f.x), "=f"(f.y) : "l"(v)); return f;
}
__device__ __forceinline__ u64 ffma2(u64 a, u64 b, u64 c) {
    u64 d; asm("fma.rn.f32x2 %0, %1, %2, %3;" : "=l"(d) : "l"(a), "l"(b), "l"(c)); return d;
}
__device__ __forceinline__ u64 fadd2(u64 a, u64 b) {
    u64 d; asm("add.rn.f32x2 %0, %1, %2;" : "=l"(d) : "l"(a), "l"(b)); return d;
}

__device__ __forceinline__ float warp_sum(float v) {
    #pragma unroll
    for (int off = 16; off >= 1; off >>= 1)
        v += __shfl_xor_sync(0xffffffffu, v, off);
    return v;
}

// ---------------- cp.async helpers ----------------
#define CP16(dst_u32, src_ptr) \
    asm volatile("cp.async.cg.shared.global [%0], [%1], 16;" :: "r"(dst_u32), "l"(src_ptr))
#define CP_COMMIT() asm volatile("cp.async.commit_group;" ::: "memory")
#define CP_WAIT0()  asm volatile("cp.async.wait_group 0;" ::: "memory")
#define CP_WAIT1()  asm volatile("cp.async.wait_group 1;" ::: "memory")

// ================= Kernel 1: factored attention + LN1 =================
// per warp: one x-token, double-buffered u prefetch via cp.async.
//   logit_{t,g} = u_t . wkq_g + bkq_g,   wkq_g = Wk @ q_g
//   out_g       = (sum_t a_tg u_t) @ Wv + bv

#define WARP_SLAB 2592
// per-warp slab: su0[0:1088) su1[1088:2176) swkq[2176:2440) sqa[2440:2504)
//                sbkq[2504:2512) sx[2512:2576)

__device__ __forceinline__ const float* u_base(const float* u, int tok, int& to) {
    int b = tok / N_TOK;
    int n = tok - b * N_TOK;
    int off0, off1, nl;
    if (n < 4096)      { to = 4;  off0 = 0;     off1 = 24576; nl = n; }
    else if (n < 6144) { to = 8;  off0 = 8192;  off1 = 32768; nl = n - 4096; }
    else               { to = 16; off0 = 16384; off1 = 40960; nl = n - 6144; }
    int f = nl * to;
    int g = (f < 8192) ? (off0 + f) : (off1 + f - 8192);
    return u + ((size_t)b * U_TOK + g) * 64;
}

__device__ __forceinline__ void prefetch_u(const float* ub, float* su, int to, int lane) {
    unsigned s = (unsigned)__cvta_generic_to_shared(su);
    const float4* up4 = (const float4*)ub;
    for (int i = lane; i < to * 16; i += 32) {
        int t = i >> 4, dd = (i & 15) << 2;
        CP16(s + (unsigned)(t * 68 + dd) * 4u, up4 + i);
    }
}

__global__ void __launch_bounds__(128, 2) attn_kernel(
    const float* __restrict__ u, const float* __restrict__ x,
    const float* __restrict__ Wk, const float* __restrict__ bk,
    const float* __restrict__ Wq, const float* __restrict__ bq,
    const float* __restrict__ Wv, const float* __restrict__ bv,
    const float* __restrict__ g1, const float* __restrict__ be1)
{
    extern __shared__ float sm1[];
    float* sWq  = sm1;              // 4096  [d][c]
    float* sWkT = sm1 + 4096;       // 4096  [c][d]
    float* sWv  = sm1 + 8192;       // 4096  [d][c]
    float* sB   = sm1 + 12288;      // 320
    float* sSlab = sm1 + 12608;     // 4 warps * WARP_SLAB

    int tid = threadIdx.x;
    for (int i = tid; i < 4096; i += 128) {
        sWq[i] = Wq[i];
        sWv[i] = Wv[i];
        int cc = i >> 6, dd = i & 63;
        sWkT[i] = Wk[dd * 64 + cc];
    }
    if (tid < 64) {
        sB[tid]       = bk[tid];
        sB[64 + tid]  = bq[tid];
        sB[128 + tid] = bv[tid];
        sB[192 + tid] = g1[tid];
        sB[256 + tid] = be1[tid];
    }
    __syncthreads();

    int warp = tid >> 5, lane = tid & 31;
    int c = 2 * lane;
    float* base = sSlab + warp * WARP_SLAB;
    float* su0  = base;
    float* su1  = base + 1088;
    float* swkq = base + 2176;
    float* sqa  = base + 2440;   // q then softmax weights
    float* sbkq = base + 2504;
    float* sx   = base + 2512;

    float bk0 = sB[c], bk1 = sB[c + 1];
    u64 bq2 = *(const u64*)&sB[64 + c];
    u64 bv2 = *(const u64*)&sB[128 + c];
    float gg0 = sB[192 + c], gg1 = sB[192 + c + 1];
    float bb0 = sB[256 + c], bb1 = sB[256 + c + 1];

    int tt = lane >> 2, glog = lane & 3;
    int gout = lane >> 3;

    int wg = blockIdx.x * 4 + warp;
    int nwarps = gridDim.x * 4;

    int tok = wg;
    int to = 0, sel = 0;
    if (tok < TOK_TOTAL) {
        const float* ub0 = u_base(u, tok, to);
        prefetch_u(ub0, su0, to, lane);
    }
    CP_COMMIT();

    for (; tok < TOK_TOTAL; tok += nwarps) {
        float* su    = sel ? su1 : su0;
        float* snext = sel ? su0 : su1;
        int tokn = tok + nwarps;
        bool hasn = tokn < TOK_TOTAL;
        int ton = 0;
        if (hasn) {
            const float* ubn = u_base(u, tokn, ton);
            prefetch_u(ubn, snext, ton, lane);
        }
        CP_COMMIT();

        // ---- stage x, q projection (u-independent work) ----
        const float* xb = x + (size_t)tok * 64;
        sx[lane] = xb[lane];
        sx[lane + 32] = xb[lane + 32];
        __syncwarp();
        u64 qa = bq2, qb = pk2(0.f, 0.f);
        #pragma unroll 8
        for (int d = 0; d < 64; d += 4) {
            float2 x0 = *(const float2*)&sx[d];
            float2 x1 = *(const float2*)&sx[d + 2];
            qa = ffma2(*(const u64*)&sWq[d * 64 + c],       pk2(x0.x, x0.x), qa);
            qb = ffma2(*(const u64*)&sWq[(d + 1) * 64 + c], pk2(x0.y, x0.y), qb);
            qa = ffma2(*(const u64*)&sWq[(d + 2) * 64 + c], pk2(x1.x, x1.x), qa);
            qb = ffma2(*(const u64*)&sWq[(d + 3) * 64 + c], pk2(x1.y, x1.y), qb);
        }
        u64 q2 = fadd2(qa, qb);
        float2 qf = up2(q2);
        *(u64*)&sqa[c] = q2;

        float p = bk0 * qf.x + bk1 * qf.y;
        p += __shfl_xor_sync(0xffffffffu, p, 1);
        p += __shfl_xor_sync(0xffffffffu, p, 2);
        p += __shfl_xor_sync(0xffffffffu, p, 4);
        if ((lane & 7) == 0) sbkq[lane >> 3] = p;
        __syncwarp();

        // ---- wkq_g[d-pair] ----
        u64 wkql[4];
        #pragma unroll
        for (int gi = 0; gi < 4; gi++) {
            u64 a0 = pk2(0.f, 0.f), a1 = pk2(0.f, 0.f);
            #pragma unroll
            for (int c0 = 16 * gi; c0 < 16 * gi + 16; c0 += 2) {
                float2 qp = *(const float2*)&sqa[c0];
                a0 = ffma2(*(const u64*)&sWkT[c0 * 64 + c],       pk2(qp.x, qp.x), a0);
                a1 = ffma2(*(const u64*)&sWkT[(c0 + 1) * 64 + c], pk2(qp.y, qp.y), a1);
            }
            wkql[gi] = fadd2(a0, a1);
        }
        #pragma unroll
        for (int gi = 0; gi < 4; gi++)
            *(u64*)&swkq[gi * 66 + c] = wkql[gi];
        __syncwarp();

        // ---- wait for this token's u ----
        if (hasn) { CP_WAIT1(); } else { CP_WAIT0(); }
        __syncwarp();

        // ---- logits ----
        int tval = (to < 8) ? to : 8;
        float lg0 = -1e30f, lg1 = -1e30f;
        float bqg = sbkq[glog];
        if (tt < tval) {
            u64 a0 = pk2(0.f, 0.f), a1 = pk2(0.f, 0.f);
            #pragma unroll 8
            for (int d = 0; d < 64; d += 4) {
                a0 = ffma2(*(const u64*)&su[tt * 68 + d],     *(const u64*)&swkq[glog * 66 + d],     a0);
                a1 = ffma2(*(const u64*)&su[tt * 68 + d + 2], *(const u64*)&swkq[glog * 66 + d + 2], a1);
            }
            float2 s2 = up2(fadd2(a0, a1));
            lg0 = (s2.x + s2.y + bqg) * 0.125f;
        }
        if (to == 16) {
            int t = tt + 8;
            u64 a0 = pk2(0.f, 0.f), a1 = pk2(0.f, 0.f);
            #pragma unroll 8
            for (int d = 0; d < 64; d += 4) {
                a0 = ffma2(*(const u64*)&su[t * 68 + d],     *(const u64*)&swkq[glog * 66 + d],     a0);
                a1 = ffma2(*(const u64*)&su[t * 68 + d + 2], *(const u64*)&swkq[glog * 66 + d + 2], a1);
            }
            float2 s2 = up2(fadd2(a0, a1));
            lg1 = (s2.x + s2.y + bqg) * 0.125f;
        }

        // ---- softmax over t ----
        float m = fmaxf(lg0, lg1);
        m = fmaxf(m, __shfl_xor_sync(0xffffffffu, m, 4));
        m = fmaxf(m, __shfl_xor_sync(0xffffffffu, m, 8));
        m = fmaxf(m, __shfl_xor_sync(0xffffffffu, m, 16));
        float w0 = __expf(lg0 - m);
        float w1 = __expf(lg1 - m);
        float s = w0 + w1;
        s += __shfl_xor_sync(0xffffffffu, s, 4);
        s += __shfl_xor_sync(0xffffffffu, s, 8);
        s += __shfl_xor_sync(0xffffffffu, s, 16);
        float inv = 1.0f / s;
        if (tt < tval) sqa[lane] = w0 * inv;
        if (to == 16)  sqa[lane + 32] = w1 * inv;
        __syncwarp();

        // ---- r_g = sum_t a_tg u_t ----
        u64 r0 = pk2(0.f, 0.f), r1 = pk2(0.f, 0.f), r2 = pk2(0.f, 0.f), r3 = pk2(0.f, 0.f);
        for (int t = 0; t < to; t++) {
            float4 a4 = *(const float4*)&sqa[t * 4];
            u64 uu = *(const u64*)&su[t * 68 + c];
            r0 = ffma2(uu, pk2(a4.x, a4.x), r0);
            r1 = ffma2(uu, pk2(a4.y, a4.y), r1);
            r2 = ffma2(uu, pk2(a4.z, a4.z), r2);
            r3 = ffma2(uu, pk2(a4.w, a4.w), r3);
        }
        __syncwarp();
        float* sr = su;   // overlay (u dead)
        *(u64*)&sr[0 * 66 + c] = r0;
        *(u64*)&sr[1 * 66 + c] = r1;
        *(u64*)&sr[2 * 66 + c] = r2;
        *(u64*)&sr[3 * 66 + c] = r3;
        __syncwarp();

        // ---- out projection ----
        u64 oa = bv2, ob = pk2(0.f, 0.f);
        #pragma unroll 8
        for (int d = 0; d < 64; d += 4) {
            float2 rp0 = *(const float2*)&sr[gout * 66 + d];
            float2 rp1 = *(const float2*)&sr[gout * 66 + d + 2];
            oa = ffma2(*(const u64*)&sWv[d * 64 + c],       pk2(rp0.x, rp0.x), oa);
            ob = ffma2(*(const u64*)&sWv[(d + 1) * 64 + c], pk2(rp0.y, rp0.y), ob);
            oa = ffma2(*(const u64*)&sWv[(d + 2) * 64 + c], pk2(rp1.x, rp1.x), oa);
            ob = ffma2(*(const u64*)&sWv[(d + 3) * 64 + c], pk2(rp1.y, rp1.y), ob);
        }
        float2 of = up2(fadd2(oa, ob));
        __syncwarp();   // sr reads done before next iteration writes this buffer

        // ---- LN1 + store ----
        float mean = warp_sum(of.x + of.y) * (1.0f / 64.0f);
        float d0 = of.x - mean, d1 = of.y - mean;
        float var = warp_sum(d0 * d0 + d1 * d1) * (1.0f / 64.0f);
        float r = rsqrtf(var + 1e-5f);
        float2 y;
        y.x = d0 * r * gg0 + bb0;
        y.y = d1 * r * gg1 + bb1;
        *(float2*)&g_z1[(size_t)tok * 64 + c] = y;

        to = ton;
        sel ^= 1;
    }
}

// ================= Kernel 2: MLP + LN2 + shortcut, 8 tokens/warp =================

__device__ __forceinline__ float gelu_exact(float v) {
    return 0.5f * v * (1.0f + erff(v * 0.70710678118654752f));
}

__global__ void __launch_bounds__(256) mlp_kernel(
    const float* __restrict__ x,
    const float* __restrict__ Wm1, const float* __restrict__ bm1,
    const float* __restrict__ Wm2, const float* __restrict__ bm2,
    const float* __restrict__ g2,  const float* __restrict__ be2,
    const float* __restrict__ Ws,  const float* __restrict__ bs,
    float* __restrict__ out)
{
    extern __shared__ float sm2[];
    float* sW1 = sm2;               // 16384  [d][256]
    float* sW2 = sm2 + 16384;       // 16384  [c][64]
    float* sWs = sm2 + 32768;       // 4096   [d][64]
    float* sB  = sm2 + 36864;       // 512
    float* sStage = sm2 + 37376;    // 8 warps * 2048

    int tid = threadIdx.x;
    for (int i = tid; i < 16384; i += 256) { sW1[i] = Wm1[i]; sW2[i] = Wm2[i]; }
    for (int i = tid; i < 4096; i += 256) sWs[i] = Ws[i];
    if (tid < 256) sB[tid] = bm1[tid];
    if (tid < 64) {
        sB[256 + tid] = bm2[tid];
        sB[320 + tid] = g2[tid];
        sB[384 + tid] = be2[tid];
        sB[448 + tid] = bs[tid];
    }
    __syncthreads();

    int warp = tid >> 5, lane = tid & 31;
    int l2 = 2 * lane;
    float* slab = sStage + warp * 2048;

    u64 bm2p = *(const u64*)&sB[256 + l2];
    u64 bsp  = *(const u64*)&sB[448 + l2];
    float gg0 = sB[320 + l2], gg1 = sB[320 + l2 + 1];
    float bb0 = sB[384 + l2], bb1 = sB[384 + l2 + 1];

    int wg = blockIdx.x * 8 + warp;
    int nw = gridDim.x * 8;

    for (int grp = wg; grp < TOK_TOTAL / 8; grp += nw) {
        int tok0 = grp * 8;

        // stage z1 (8 tokens) into slab[t][0:64)
        #pragma unroll
        for (int t = 0; t < 8; t++) {
            slab[t * 256 + lane]      = g_z1[(size_t)(tok0 + t) * 64 + lane];
            slab[t * 256 + lane + 32] = g_z1[(size_t)(tok0 + t) * 64 + lane + 32];
        }
        __syncwarp();

        // ---- matvec1: 64 -> 256, h[k][t] in regs ----
        u64 h[4][8];
        #pragma unroll
        for (int k = 0; k < 4; k++) {
            u64 bm = *(const u64*)&sB[64 * k + l2];
            #pragma unroll
            for (int t = 0; t < 8; t++) h[k][t] = bm;
        }
        #pragma unroll 2
        for (int d = 0; d < 64; d += 2) {
            u64 w0[4], w1[4];
            #pragma unroll
            for (int k = 0; k < 4; k++) {
                w0[k] = *(const u64*)&sW1[d * 256 + 64 * k + l2];
                w1[k] = *(const u64*)&sW1[(d + 1) * 256 + 64 * k + l2];
            }
            #pragma unroll
            for (int t = 0; t < 8; t++) {
                float2 zv = *(const float2*)&slab[t * 256 + d];
                u64 z0 = pk2(zv.x, zv.x);
                u64 z1 = pk2(zv.y, zv.y);
                #pragma unroll
                for (int k = 0; k < 4; k++) {
                    h[k][t] = ffma2(w0[k], z0, h[k][t]);
                    h[k][t] = ffma2(w1[k], z1, h[k][t]);
                }
            }
        }
        __syncwarp();

        // ---- gelu + stage h ----
        #pragma unroll
        for (int t = 0; t < 8; t++) {
            #pragma unroll
            for (int k = 0; k < 4; k++) {
                float2 hv = up2(h[k][t]);
                hv.x = gelu_exact(hv.x);
                hv.y = gelu_exact(hv.y);
                *(u64*)&slab[t * 256 + 64 * k + l2] = pk2(hv.x, hv.y);
            }
        }
        __syncwarp();

        // ---- matvec2: 256 -> 64, float4 activation broadcast ----
        u64 o[8];
        #pragma unroll
        for (int t = 0; t < 8; t++) o[t] = bm2p;
        #pragma unroll 2
        for (int cb = 0; cb < 256; cb += 4) {
            u64 wA = *(const u64*)&sW2[cb * 64 + l2];
            u64 wB = *(const u64*)&sW2[(cb + 1) * 64 + l2];
            u64 wC = *(const u64*)&sW2[(cb + 2) * 64 + l2];
            u64 wD = *(const u64*)&sW2[(cb + 3) * 64 + l2];
            #pragma unroll
            for (int t = 0; t < 8; t++) {
                float4 hv = *(const float4*)&slab[t * 256 + cb];
                o[t] = ffma2(wA, pk2(hv.x, hv.x), o[t]);
                o[t] = ffma2(wB, pk2(hv.y, hv.y), o[t]);
                o[t] = ffma2(wC, pk2(hv.z, hv.z), o[t]);
                o[t] = ffma2(wD, pk2(hv.w, hv.w), o[t]);
            }
        }
        __syncwarp();

        // ---- stage x, shortcut matvec ----
        #pragma unroll
        for (int t = 0; t < 8; t++) {
            slab[t * 256 + lane]      = x[(size_t)(tok0 + t) * 64 + lane];
            slab[t * 256 + lane + 32] = x[(size_t)(tok0 + t) * 64 + lane + 32];
        }
        __syncwarp();
        u64 sc[8];
        #pragma unroll
        for (int t = 0; t < 8; t++) sc[t] = bsp;
        #pragma unroll 2
        for (int d = 0; d < 64; d += 4) {
            u64 wA = *(const u64*)&sWs[d * 64 + l2];
            u64 wB = *(const u64*)&sWs[(d + 1) * 64 + l2];
            u64 wC = *(const u64*)&sWs[(d + 2) * 64 + l2];
            u64 wD = *(const u64*)&sWs[(d + 3) * 64 + l2];
            #pragma unroll
            for (int t = 0; t < 8; t++) {
                float4 xv = *(const float4*)&slab[t * 256 + d];
                sc[t] = ffma2(wA, pk2(xv.x, xv.x), sc[t]);
                sc[t] = ffma2(wB, pk2(xv.y, xv.y), sc[t]);
                sc[t] = ffma2(wC, pk2(xv.z, xv.z), sc[t]);
                sc[t] = ffma2(wD, pk2(xv.w, xv.w), sc[t]);
            }
        }
        __syncwarp();

        // ---- LN2 + shortcut + write ----
        #pragma unroll
        for (int t = 0; t < 8; t++) {
            float2 ov = up2(o[t]);
            float mean = warp_sum(ov.x + ov.y) * (1.0f / 64.0f);
            float d0 = ov.x - mean, d1 = ov.y - mean;
            float var = warp_sum(d0 * d0 + d1 * d1) * (1.0f / 64.0f);
            float r = rsqrtf(var + 1e-5f);
            float2 scv = up2(sc[t]);
            float2 y;
            y.x = d0 * r * gg0 + bb0 + scv.x;
            y.y = d1 * r * gg1 + bb1 + scv.y;
            *(float2*)&out[(size_t)(tok0 + t) * 64 + l2] = y;
        }
    }
}

// ================= launch =================
extern "C" void kernel_launch(void* const* d_in, const int* in_sizes, int n_in,
                              void* d_out, int out_size)
{
    const float* u   = (const float*)d_in[0];
    const float* x   = (const float*)d_in[1];
    const float* Wk  = (const float*)d_in[2];
    const float* bk  = (const float*)d_in[3];
    const float* Wq  = (const float*)d_in[4];
    const float* bq  = (const float*)d_in[5];
    const float* Wv  = (const float*)d_in[6];
    const float* bv  = (const float*)d_in[7];
    const float* g1  = (const float*)d_in[8];
    const float* be1 = (const float*)d_in[9];
    const float* Wm1 = (const float*)d_in[10];
    const float* bm1 = (const float*)d_in[11];
    const float* Wm2 = (const float*)d_in[12];
    const float* bm2 = (const float*)d_in[13];
    const float* g2  = (const float*)d_in[14];
    const float* be2 = (const float*)d_in[15];
    const float* Ws  = (const float*)d_in[16];
    const float* bs  = (const float*)d_in[17];
    float* out = (float*)d_out;

    const int smem1 = (12608 + 4 * WARP_SLAB) * 4;   // 91904 B
    const int smem2 = 53760 * 4;                     // 215040 B
    cudaFuncSetAttribute(attn_kernel, cudaFuncAttributeMaxDynamicSharedMemorySize, smem1);
    cudaFuncSetAttribute(mlp_kernel,  cudaFuncAttributeMaxDynamicSharedMemorySize, smem2);

    attn_kernel<<<592, 128, smem1>>>(u, x, Wk, bk, Wq, bq, Wv, bv, g1, be1);
    mlp_kernel<<<148, 256, smem2>>>(x, Wm1, bm1, Wm2, bm2, g2, be2, Ws, bs, out);
}

// round 6
// speedup vs baseline: 1.1109x; 1.1109x over previous
#include <cuda_runtime.h>
#include <math.h>

#define TOK_TOTAL 57344   // B*N = 8*7168
#define U_TOK     49152
#define N_TOK     7168

typedef unsigned long long u64;

// scratch: z1 = LN1(attention output), [B*N, 64] fp32
__device__ float g_z1[TOK_TOTAL * 64];

// ---------------- packed f32x2 helpers (sm_100+) ----------------
__device__ __forceinline__ u64 pk2(float x, float y) {
    u64 r; asm("mov.b64 %0, {%1,%2};" : "=l"(r) : "f"(x), "f"(y)); return r;
}
__device__ __forceinline__ float2 up2(u64 v) {
    float2 f; asm("mov.b64 {%0,%1}, %2;" : "=f"(f.x), "=f"(f.y) : "l"(v)); return f;
}
__device__ __forceinline__ u64 ffma2(u64 a, u64 b, u64 c) {
    u64 d; asm("fma.rn.f32x2 %0, %1, %2, %3;" : "=l"(d) : "l"(a), "l"(b), "l"(c)); return d;
}
__device__ __forceinline__ u64 fadd2(u64 a, u64 b) {
    u64 d; asm("add.rn.f32x2 %0, %1, %2;" : "=l"(d) : "l"(a), "l"(b)); return d;
}

__device__ __forceinline__ float warp_sum(float v) {
    #pragma unroll
    for (int off = 16; off >= 1; off >>= 1)
        v += __shfl_xor_sync(0xffffffffu, v, off);
    return v;
}

// ---------------- cp.async helpers ----------------
#define CP16(dst_u32, src_ptr) \
    asm volatile("cp.async.cg.shared.global [%0], [%1], 16;" :: "r"(dst_u32), "l"(src_ptr))
#define CP_COMMIT() asm volatile("cp.async.commit_group;" ::: "memory")
#define CP_WAIT0()  asm volatile("cp.async.wait_group 0;" ::: "memory")
#define CP_WAIT1()  asm volatile("cp.async.wait_group 1;" ::: "memory")

// ================= Kernel 1: factored attention + LN1 =================
// 512 threads = 16 warps, 1 block/SM. per warp: one x-token,
// double-buffered u prefetch via cp.async.

#define WARP_SLAB 2592
// per-warp slab: su0[0:1088) su1[1088:2176) swkq[2176:2440) sqa[2440:2504)
//                sbkq[2504:2512) sx[2512:2576)

__device__ __forceinline__ const float* u_base(const float* u, int tok, int& to) {
    int b = tok / N_TOK;
    int n = tok - b * N_TOK;
    int off0, off1, nl;
    if (n < 4096)      { to = 4;  off0 = 0;     off1 = 24576; nl = n; }
    else if (n < 6144) { to = 8;  off0 = 8192;  off1 = 32768; nl = n - 4096; }
    else               { to = 16; off0 = 16384; off1 = 40960; nl = n - 6144; }
    int f = nl * to;
    int g = (f < 8192) ? (off0 + f) : (off1 + f - 8192);
    return u + ((size_t)b * U_TOK + g) * 64;
}

__device__ __forceinline__ void prefetch_u(const float* ub, float* su, int to, int lane) {
    unsigned s = (unsigned)__cvta_generic_to_shared(su);
    const float4* up4 = (const float4*)ub;
    for (int i = lane; i < to * 16; i += 32) {
        int t = i >> 4, dd = (i & 15) << 2;
        CP16(s + (unsigned)(t * 68 + dd) * 4u, up4 + i);
    }
}

__global__ void __launch_bounds__(512, 1) attn_kernel(
    const float* __restrict__ u, const float* __restrict__ x,
    const float* __restrict__ Wk, const float* __restrict__ bk,
    const float* __restrict__ Wq, const float* __restrict__ bq,
    const float* __restrict__ Wv, const float* __restrict__ bv,
    const float* __restrict__ g1, const float* __restrict__ be1)
{
    extern __shared__ float sm1[];
    float* sWq  = sm1;              // 4096  [d][c]
    float* sWkT = sm1 + 4096;       // 4096  [c][d]
    float* sWv  = sm1 + 8192;       // 4096  [d][c]
    float* sB   = sm1 + 12288;      // 320
    float* sSlab = sm1 + 12608;     // 16 warps * WARP_SLAB

    int tid = threadIdx.x;
    for (int i = tid; i < 4096; i += 512) {
        sWq[i] = Wq[i];
        sWv[i] = Wv[i];
        int cc = i >> 6, dd = i & 63;
        sWkT[i] = Wk[dd * 64 + cc];
    }
    if (tid < 64) {
        sB[tid]       = bk[tid];
        sB[64 + tid]  = bq[tid];
        sB[128 + tid] = bv[tid];
        sB[192 + tid] = g1[tid];
        sB[256 + tid] = be1[tid];
    }
    __syncthreads();

    int warp = tid >> 5, lane = tid & 31;
    int c = 2 * lane;
    float* base = sSlab + warp * WARP_SLAB;
    float* su0  = base;
    float* su1  = base + 1088;
    float* swkq = base + 2176;
    float* sqa  = base + 2440;   // q then softmax weights
    float* sbkq = base + 2504;
    float* sx   = base + 2512;

    float bk0 = sB[c], bk1 = sB[c + 1];
    u64 bq2 = *(const u64*)&sB[64 + c];
    u64 bv2 = *(const u64*)&sB[128 + c];
    float gg0 = sB[192 + c], gg1 = sB[192 + c + 1];
    float bb0 = sB[256 + c], bb1 = sB[256 + c + 1];

    int tt = lane >> 2, glog = lane & 3;
    int gout = lane >> 3;

    int wg = blockIdx.x * 16 + warp;
    int nwarps = gridDim.x * 16;

    int tok = wg;
    int to = 0, sel = 0;
    if (tok < TOK_TOTAL) {
        const float* ub0 = u_base(u, tok, to);
        prefetch_u(ub0, su0, to, lane);
    }
    CP_COMMIT();

    for (; tok < TOK_TOTAL; tok += nwarps) {
        float* su    = sel ? su1 : su0;
        float* snext = sel ? su0 : su1;
        int tokn = tok + nwarps;
        bool hasn = tokn < TOK_TOTAL;
        int ton = 0;
        if (hasn) {
            const float* ubn = u_base(u, tokn, ton);
            prefetch_u(ubn, snext, ton, lane);
        }
        CP_COMMIT();

        // ---- stage x, q projection (u-independent work) ----
        const float* xb = x + (size_t)tok * 64;
        sx[lane] = xb[lane];
        sx[lane + 32] = xb[lane + 32];
        __syncwarp();
        u64 qa = bq2, qb = pk2(0.f, 0.f);
        #pragma unroll 8
        for (int d = 0; d < 64; d += 4) {
            float2 x0 = *(const float2*)&sx[d];
            float2 x1 = *(const float2*)&sx[d + 2];
            qa = ffma2(*(const u64*)&sWq[d * 64 + c],       pk2(x0.x, x0.x), qa);
            qb = ffma2(*(const u64*)&sWq[(d + 1) * 64 + c], pk2(x0.y, x0.y), qb);
            qa = ffma2(*(const u64*)&sWq[(d + 2) * 64 + c], pk2(x1.x, x1.x), qa);
            qb = ffma2(*(const u64*)&sWq[(d + 3) * 64 + c], pk2(x1.y, x1.y), qb);
        }
        u64 q2 = fadd2(qa, qb);
        float2 qf = up2(q2);
        *(u64*)&sqa[c] = q2;

        float p = bk0 * qf.x + bk1 * qf.y;
        p += __shfl_xor_sync(0xffffffffu, p, 1);
        p += __shfl_xor_sync(0xffffffffu, p, 2);
        p += __shfl_xor_sync(0xffffffffu, p, 4);
        if ((lane & 7) == 0) sbkq[lane >> 3] = p;
        __syncwarp();

        // ---- wkq_g[d-pair] ----
        u64 wkql[4];
        #pragma unroll
        for (int gi = 0; gi < 4; gi++) {
            u64 a0 = pk2(0.f, 0.f), a1 = pk2(0.f, 0.f);
            #pragma unroll
            for (int c0 = 16 * gi; c0 < 16 * gi + 16; c0 += 2) {
                float2 qp = *(const float2*)&sqa[c0];
                a0 = ffma2(*(const u64*)&sWkT[c0 * 64 + c],       pk2(qp.x, qp.x), a0);
                a1 = ffma2(*(const u64*)&sWkT[(c0 + 1) * 64 + c], pk2(qp.y, qp.y), a1);
            }
            wkql[gi] = fadd2(a0, a1);
        }
        #pragma unroll
        for (int gi = 0; gi < 4; gi++)
            *(u64*)&swkq[gi * 66 + c] = wkql[gi];
        __syncwarp();

        // ---- wait for this token's u ----
        if (hasn) { CP_WAIT1(); } else { CP_WAIT0(); }
        __syncwarp();

        // ---- logits ----
        int tval = (to < 8) ? to : 8;
        float lg0 = -1e30f, lg1 = -1e30f;
        float bqg = sbkq[glog];
        if (tt < tval) {
            u64 a0 = pk2(0.f, 0.f), a1 = pk2(0.f, 0.f);
            #pragma unroll 8
            for (int d = 0; d < 64; d += 4) {
                a0 = ffma2(*(const u64*)&su[tt * 68 + d],     *(const u64*)&swkq[glog * 66 + d],     a0);
                a1 = ffma2(*(const u64*)&su[tt * 68 + d + 2], *(const u64*)&swkq[glog * 66 + d + 2], a1);
            }
            float2 s2 = up2(fadd2(a0, a1));
            lg0 = (s2.x + s2.y + bqg) * 0.125f;
        }
        if (to == 16) {
            int t = tt + 8;
            u64 a0 = pk2(0.f, 0.f), a1 = pk2(0.f, 0.f);
            #pragma unroll 8
            for (int d = 0; d < 64; d += 4) {
                a0 = ffma2(*(const u64*)&su[t * 68 + d],     *(const u64*)&swkq[glog * 66 + d],     a0);
                a1 = ffma2(*(const u64*)&su[t * 68 + d + 2], *(const u64*)&swkq[glog * 66 + d + 2], a1);
            }
            float2 s2 = up2(fadd2(a0, a1));
            lg1 = (s2.x + s2.y + bqg) * 0.125f;
        }

        // ---- softmax over t ----
        float m = fmaxf(lg0, lg1);
        m = fmaxf(m, __shfl_xor_sync(0xffffffffu, m, 4));
        m = fmaxf(m, __shfl_xor_sync(0xffffffffu, m, 8));
        m = fmaxf(m, __shfl_xor_sync(0xffffffffu, m, 16));
        float w0 = __expf(lg0 - m);
        float w1 = __expf(lg1 - m);
        float s = w0 + w1;
        s += __shfl_xor_sync(0xffffffffu, s, 4);
        s += __shfl_xor_sync(0xffffffffu, s, 8);
        s += __shfl_xor_sync(0xffffffffu, s, 16);
        float inv = 1.0f / s;
        if (tt < tval) sqa[lane] = w0 * inv;
        if (to == 16)  sqa[lane + 32] = w1 * inv;
        __syncwarp();

        // ---- r_g = sum_t a_tg u_t ----
        u64 r0 = pk2(0.f, 0.f), r1 = pk2(0.f, 0.f), r2 = pk2(0.f, 0.f), r3 = pk2(0.f, 0.f);
        for (int t = 0; t < to; t++) {
            float4 a4 = *(const float4*)&sqa[t * 4];
            u64 uu = *(const u64*)&su[t * 68 + c];
            r0 = ffma2(uu, pk2(a4.x, a4.x), r0);
            r1 = ffma2(uu, pk2(a4.y, a4.y), r1);
            r2 = ffma2(uu, pk2(a4.z, a4.z), r2);
            r3 = ffma2(uu, pk2(a4.w, a4.w), r3);
        }
        __syncwarp();
        float* sr = su;   // overlay (u dead)
        *(u64*)&sr[0 * 66 + c] = r0;
        *(u64*)&sr[1 * 66 + c] = r1;
        *(u64*)&sr[2 * 66 + c] = r2;
        *(u64*)&sr[3 * 66 + c] = r3;
        __syncwarp();

        // ---- out projection ----
        u64 oa = bv2, ob = pk2(0.f, 0.f);
        #pragma unroll 8
        for (int d = 0; d < 64; d += 4) {
            float2 rp0 = *(const float2*)&sr[gout * 66 + d];
            float2 rp1 = *(const float2*)&sr[gout * 66 + d + 2];
            oa = ffma2(*(const u64*)&sWv[d * 64 + c],       pk2(rp0.x, rp0.x), oa);
            ob = ffma2(*(const u64*)&sWv[(d + 1) * 64 + c], pk2(rp0.y, rp0.y), ob);
            oa = ffma2(*(const u64*)&sWv[(d + 2) * 64 + c], pk2(rp1.x, rp1.x), oa);
            ob = ffma2(*(const u64*)&sWv[(d + 3) * 64 + c], pk2(rp1.y, rp1.y), ob);
        }
        float2 of = up2(fadd2(oa, ob));
        __syncwarp();   // sr reads done before next iteration writes this buffer

        // ---- LN1 + store ----
        float mean = warp_sum(of.x + of.y) * (1.0f / 64.0f);
        float d0 = of.x - mean, d1 = of.y - mean;
        float var = warp_sum(d0 * d0 + d1 * d1) * (1.0f / 64.0f);
        float r = rsqrtf(var + 1e-5f);
        float2 y;
        y.x = d0 * r * gg0 + bb0;
        y.y = d1 * r * gg1 + bb1;
        *(float2*)&g_z1[(size_t)tok * 64 + c] = y;

        to = ton;
        sel ^= 1;
    }
}

// ================= Kernel 2: MLP + LN2 + shortcut =================
// 384 threads = 12 warps, 8 tokens/warp, two-pass over the 256 hidden
// channels so the h slab is only 8x128 per warp.

__device__ __forceinline__ float gelu_exact(float v) {
    return 0.5f * v * (1.0f + erff(v * 0.70710678118654752f));
}

#define MLP_SLAB 1536   // slab1 (8x128) + slab2 (8x64)

__global__ void __launch_bounds__(384, 1) mlp_kernel(
    const float* __restrict__ x,
    const float* __restrict__ Wm1, const float* __restrict__ bm1,
    const float* __restrict__ Wm2, const float* __restrict__ bm2,
    const float* __restrict__ g2,  const float* __restrict__ be2,
    const float* __restrict__ Ws,  const float* __restrict__ bs,
    float* __restrict__ out)
{
    extern __shared__ float sm2[];
    float* sW1 = sm2;               // 16384  [d][256]
    float* sW2 = sm2 + 16384;       // 16384  [cb][64]
    float* sWs = sm2 + 32768;       // 4096   [d][64]
    float* sB  = sm2 + 36864;       // 512
    float* sStage = sm2 + 37376;    // 12 warps * MLP_SLAB

    int tid = threadIdx.x;
    for (int i = tid; i < 16384; i += 384) { sW1[i] = Wm1[i]; sW2[i] = Wm2[i]; }
    for (int i = tid; i < 4096; i += 384) sWs[i] = Ws[i];
    if (tid < 256) sB[tid] = bm1[tid];
    if (tid < 64) {
        sB[256 + tid] = bm2[tid];
        sB[320 + tid] = g2[tid];
        sB[384 + tid] = be2[tid];
        sB[448 + tid] = bs[tid];
    }
    __syncthreads();

    int warp = tid >> 5, lane = tid & 31;
    int l2 = 2 * lane;
    float* slab1 = sStage + warp * MLP_SLAB;        // 8 x 128 (h half)
    float* slab2 = slab1 + 1024;                    // 8 x 64  (z then x)

    u64 bm2p = *(const u64*)&sB[256 + l2];
    u64 bsp  = *(const u64*)&sB[448 + l2];
    float gg0 = sB[320 + l2], gg1 = sB[320 + l2 + 1];
    float bb0 = sB[384 + l2], bb1 = sB[384 + l2 + 1];

    int wg = blockIdx.x * 12 + warp;
    int nw = gridDim.x * 12;

    for (int grp = wg; grp < TOK_TOTAL / 8; grp += nw) {
        int tok0 = grp * 8;

        // stage z (8 tokens) into slab2
        #pragma unroll
        for (int t = 0; t < 8; t++) {
            slab2[t * 64 + lane]      = g_z1[(size_t)(tok0 + t) * 64 + lane];
            slab2[t * 64 + lane + 32] = g_z1[(size_t)(tok0 + t) * 64 + lane + 32];
        }
        __syncwarp();

        u64 o[8];
        #pragma unroll
        for (int t = 0; t < 8; t++) o[t] = bm2p;

        // ---- two passes over hidden halves ----
        #pragma unroll
        for (int half = 0; half < 2; half++) {
            int k0 = half * 2;   // k = k0, k0+1

            // mv1: 64 -> 128 (channels 64*k0 .. 64*k0+127)
            u64 h[2][8];
            #pragma unroll
            for (int k = 0; k < 2; k++) {
                u64 bm = *(const u64*)&sB[64 * (k0 + k) + l2];
                #pragma unroll
                for (int t = 0; t < 8; t++) h[k][t] = bm;
            }
            #pragma unroll 4
            for (int d = 0; d < 64; d += 2) {
                u64 w00 = *(const u64*)&sW1[d * 256 + 64 * k0 + l2];
                u64 w01 = *(const u64*)&sW1[d * 256 + 64 * (k0 + 1) + l2];
                u64 w10 = *(const u64*)&sW1[(d + 1) * 256 + 64 * k0 + l2];
                u64 w11 = *(const u64*)&sW1[(d + 1) * 256 + 64 * (k0 + 1) + l2];
                #pragma unroll
                for (int t = 0; t < 8; t++) {
                    float2 zv = *(const float2*)&slab2[t * 64 + d];
                    u64 z0 = pk2(zv.x, zv.x);
                    u64 z1 = pk2(zv.y, zv.y);
                    h[0][t] = ffma2(w00, z0, h[0][t]);
                    h[1][t] = ffma2(w01, z0, h[1][t]);
                    h[0][t] = ffma2(w10, z1, h[0][t]);
                    h[1][t] = ffma2(w11, z1, h[1][t]);
                }
            }

            // gelu + stage h half into slab1
            #pragma unroll
            for (int t = 0; t < 8; t++) {
                #pragma unroll
                for (int k = 0; k < 2; k++) {
                    float2 hv = up2(h[k][t]);
                    hv.x = gelu_exact(hv.x);
                    hv.y = gelu_exact(hv.y);
                    *(u64*)&slab1[t * 128 + 64 * k + l2] = pk2(hv.x, hv.y);
                }
            }
            __syncwarp();

            // mv2 partial: 128 hidden channels of this half
            int cb0 = half * 128;
            #pragma unroll 2
            for (int j = 0; j < 128; j += 4) {
                u64 wA = *(const u64*)&sW2[(cb0 + j) * 64 + l2];
                u64 wB = *(const u64*)&sW2[(cb0 + j + 1) * 64 + l2];
                u64 wC = *(const u64*)&sW2[(cb0 + j + 2) * 64 + l2];
                u64 wD = *(const u64*)&sW2[(cb0 + j + 3) * 64 + l2];
                #pragma unroll
                for (int t = 0; t < 8; t++) {
                    float4 hv = *(const float4*)&slab1[t * 128 + j];
                    o[t] = ffma2(wA, pk2(hv.x, hv.x), o[t]);
                    o[t] = ffma2(wB, pk2(hv.y, hv.y), o[t]);
                    o[t] = ffma2(wC, pk2(hv.z, hv.z), o[t]);
                    o[t] = ffma2(wD, pk2(hv.w, hv.w), o[t]);
                }
            }
            __syncwarp();   // slab1 reads done (before next half overwrites)
        }

        // ---- stage x into slab2, shortcut matvec ----
        #pragma unroll
        for (int t = 0; t < 8; t++) {
            slab2[t * 64 + lane]      = x[(size_t)(tok0 + t) * 64 + lane];
            slab2[t * 64 + lane + 32] = x[(size_t)(tok0 + t) * 64 + lane + 32];
        }
        __syncwarp();
        u64 sc[8];
        #pragma unroll
        for (int t = 0; t < 8; t++) sc[t] = bsp;
        #pragma unroll 2
        for (int d = 0; d < 64; d += 4) {
            u64 wA = *(const u64*)&sWs[d * 64 + l2];
            u64 wB = *(const u64*)&sWs[(d + 1) * 64 + l2];
            u64 wC = *(const u64*)&sWs[(d + 2) * 64 + l2];
            u64 wD = *(const u64*)&sWs[(d + 3) * 64 + l2];
            #pragma unroll
            for (int t = 0; t < 8; t++) {
                float4 xv = *(const float4*)&slab2[t * 64 + d];
                sc[t] = ffma2(wA, pk2(xv.x, xv.x), sc[t]);
                sc[t] = ffma2(wB, pk2(xv.y, xv.y), sc[t]);
                sc[t] = ffma2(wC, pk2(xv.z, xv.z), sc[t]);
                sc[t] = ffma2(wD, pk2(xv.w, xv.w), sc[t]);
            }
        }
        __syncwarp();

        // ---- LN2 + shortcut + write ----
        #pragma unroll
        for (int t = 0; t < 8; t++) {
            float2 ov = up2(o[t]);
            float mean = warp_sum(ov.x + ov.y) * (1.0f / 64.0f);
            float d0 = ov.x - mean, d1 = ov.y - mean;
            float var = warp_sum(d0 * d0 + d1 * d1) * (1.0f / 64.0f);
            float r = rsqrtf(var + 1e-5f);
            float2 scv = up2(sc[t]);
            float2 y;
            y.x = d0 * r * gg0 + bb0 + scv.x;
            y.y = d1 * r * gg1 + bb1 + scv.y;
            *(float2*)&out[(size_t)(tok0 + t) * 64 + l2] = y;
        }
    }
}

// ================= launch =================
extern "C" void kernel_launch(void* const* d_in, const int* in_sizes, int n_in,
                              void* d_out, int out_size)
{
    const float* u   = (const float*)d_in[0];
    const float* x   = (const float*)d_in[1];
    const float* Wk  = (const float*)d_in[2];
    const float* bk  = (const float*)d_in[3];
    const float* Wq  = (const float*)d_in[4];
    const float* bq  = (const float*)d_in[5];
    const float* Wv  = (const float*)d_in[6];
    const float* bv  = (const float*)d_in[7];
    const float* g1  = (const float*)d_in[8];
    const float* be1 = (const float*)d_in[9];
    const float* Wm1 = (const float*)d_in[10];
    const float* bm1 = (const float*)d_in[11];
    const float* Wm2 = (const float*)d_in[12];
    const float* bm2 = (const float*)d_in[13];
    const float* g2  = (const float*)d_in[14];
    const float* be2 = (const float*)d_in[15];
    const float* Ws  = (const float*)d_in[16];
    const float* bs  = (const float*)d_in[17];
    float* out = (float*)d_out;

    const int smem1 = (12608 + 16 * WARP_SLAB) * 4;   // 216320 B
    const int smem2 = (37376 + 12 * MLP_SLAB) * 4;    // 223232 B
    cudaFuncSetAttribute(attn_kernel, cudaFuncAttributeMaxDynamicSharedMemorySize, smem1);
    cudaFuncSetAttribute(mlp_kernel,  cudaFuncAttributeMaxDynamicSharedMemorySize, smem2);

    attn_kernel<<<148, 512, smem1>>>(u, x, Wk, bk, Wq, bq, Wv, bv, g1, be1);
    mlp_kernel<<<148, 384, smem2>>>(x, Wm1, bm1, Wm2, bm2, g2, be2, Ws, bs, out);
}